// round 9
// baseline (speedup 1.0000x reference)
#include <cuda_runtime.h>
#include <cuda_bf16.h>
#include <cstdint>

// Z = XW + softmax(relu(M M^T)) @ XW + bias
// B=4, S=4096, F=64, K=32, fp32.
// Fixed-shift softmax: relu clamps scores to [0, ~88]; exp(s-40) always
// finite/normal, and (sum p*v)/(sum p) == softmax exactly.
//
// Tensor path via arch-neutral mma.sync (m16n8k16 bf16), ldmatrix, cp.async.
// Scores: 3-term bf16 split (qh*kh + ql*kh + qh*kl).
// PV: P rounded to bf16; row sums computed from the ROUNDED p so softmax
// renormalization cancels P's rounding error. V keeps hi+lo terms.
// 16 q-rows per warp (1 m-frag) -> ~100 regs -> 5 blocks/SM (20 warps),
// grid 2048 -> 2.77 waves @ 740 slots (small tail).

#define SB 4
#define SS 4096
#define SF 64
#define SK 32
#define NSPLIT 8
#define TILES (SS / NSPLIT / 64)  // 8 key tiles of 64 per block

static __device__ float g_Xw[SB * SS * SF];              // X @ W
static __device__ float g_po[NSPLIT * SB * SS * SF];     // partial o
static __device__ float g_pl[NSPLIT * SB * SS];          // partial row sums
static __device__ unsigned short g_Mhi[SB * SS * SK];    // M split hi
static __device__ unsigned short g_Mlo[SB * SS * SK];    // M split lo
static __device__ unsigned short g_VThi[SB * SF * SS];   // (Xw)^T split hi
static __device__ unsigned short g_VTlo[SB * SF * SS];   // (Xw)^T split lo

// ---------------- helpers ----------------
__device__ __forceinline__ uint32_t pack_bf16(float lo, float hi) {
    uint32_t r;
    asm("cvt.rn.bf16x2.f32 %0, %1, %2;" : "=r"(r) : "f"(hi), "f"(lo));
    return r;
}
__device__ __forceinline__ float bf_lo(uint32_t p) {
    return __uint_as_float(p << 16);
}
__device__ __forceinline__ float bf_hi(uint32_t p) {
    return __uint_as_float(p & 0xffff0000u);
}
__device__ __forceinline__ float fast_exp40(float s) {
    // exp(max(s,0) - 40) = 2^(max(s,0)*log2e - 40*log2e)
    float t = fmaxf(s, 0.f) * 1.44269504089f - 57.7078016356f;
    float r;
    asm("ex2.approx.f32 %0, %1;" : "=f"(r) : "f"(t));
    return r;
}
__device__ __forceinline__ void mma_bf16(float* d, const uint32_t* a,
                                         const uint32_t* b) {
    asm volatile(
        "mma.sync.aligned.m16n8k16.row.col.f32.bf16.bf16.f32 "
        "{%0,%1,%2,%3}, {%4,%5,%6,%7}, {%8,%9}, {%0,%1,%2,%3};"
        : "+f"(d[0]), "+f"(d[1]), "+f"(d[2]), "+f"(d[3])
        : "r"(a[0]), "r"(a[1]), "r"(a[2]), "r"(a[3]), "r"(b[0]), "r"(b[1]));
}
__device__ __forceinline__ void ldmx4(uint32_t* r, uint32_t addr) {
    asm volatile(
        "ldmatrix.sync.aligned.m8n8.x4.shared.b16 {%0,%1,%2,%3}, [%4];"
        : "=r"(r[0]), "=r"(r[1]), "=r"(r[2]), "=r"(r[3])
        : "r"(addr));
}
#define CP_ASYNC16(dst, src)                                    \
    asm volatile("cp.async.cg.shared.global [%0], [%1], 16;" :: \
                     "r"(dst), "l"(src))
#define CP_COMMIT() asm volatile("cp.async.commit_group;" ::: "memory")

// ---------------- Kernel 1: Xw = X @ W ----------------
__global__ __launch_bounds__(256) void xw_kernel(const float* __restrict__ X,
                                                 const float* __restrict__ W) {
    __shared__ __align__(16) float Ws[64 * 64];
    __shared__ __align__(16) float Xs[64 * 64];
    const int tid = threadIdx.x;
    const int row0 = blockIdx.x * 64;

    const float4* Wg = (const float4*)W;
    float4* Ws4 = (float4*)Ws;
#pragma unroll
    for (int i = 0; i < 4; i++) Ws4[tid + i * 256] = Wg[tid + i * 256];
    const float4* Xg = (const float4*)(X + (size_t)row0 * 64);
    float4* Xs4 = (float4*)Xs;
#pragma unroll
    for (int i = 0; i < 4; i++) Xs4[tid + i * 256] = Xg[tid + i * 256];
    __syncthreads();

    const int a = tid >> 4, c = tid & 15;
    float acc[4][4] = {};
#pragma unroll 16
    for (int k = 0; k < 64; k++) {
        float4 w4 = *(const float4*)(Ws + k * 64 + c * 4);
#pragma unroll
        for (int r = 0; r < 4; r++) {
            float xv = Xs[(a * 4 + r) * 64 + k];
            acc[r][0] += xv * w4.x;
            acc[r][1] += xv * w4.y;
            acc[r][2] += xv * w4.z;
            acc[r][3] += xv * w4.w;
        }
    }
    float* out = g_Xw + (size_t)row0 * 64;
#pragma unroll
    for (int r = 0; r < 4; r++)
        *(float4*)(out + (a * 4 + r) * 64 + c * 4) =
            make_float4(acc[r][0], acc[r][1], acc[r][2], acc[r][3]);
}

// ---------------- Kernel 2: split M into bf16 hi/lo ----------------
__global__ __launch_bounds__(256) void msplit_kernel(
    const float* __restrict__ M) {
    const int i = blockIdx.x * 256 + threadIdx.x;  // float4 index
    float4 v = ((const float4*)M)[i];
    uint32_t h0 = pack_bf16(v.x, v.y), h1 = pack_bf16(v.z, v.w);
    uint32_t l0 = pack_bf16(v.x - bf_lo(h0), v.y - bf_hi(h0));
    uint32_t l1 = pack_bf16(v.z - bf_lo(h1), v.w - bf_hi(h1));
    ((uint2*)g_Mhi)[i] = make_uint2(h0, h1);
    ((uint2*)g_Mlo)[i] = make_uint2(l0, l1);
}

// ---------------- Kernel 3: V^T = (Xw)^T split into bf16 hi/lo -----
__global__ __launch_bounds__(256) void vt_kernel() {
    __shared__ float T[64][65];
    const int tid = threadIdx.x;
    const int b = blockIdx.y, s0 = blockIdx.x * 64;
    const float4* src = (const float4*)(g_Xw + ((size_t)b * SS + s0) * SF);
#pragma unroll
    for (int k = 0; k < 4; k++) {
        int idx = tid + k * 256;
        int r = idx >> 4, c = idx & 15;
        float4 v = src[idx];
        T[r][c * 4 + 0] = v.x;
        T[r][c * 4 + 1] = v.y;
        T[r][c * 4 + 2] = v.z;
        T[r][c * 4 + 3] = v.w;
    }
    __syncthreads();
    const int f = tid >> 2, seg = tid & 3;
    uint32_t hb[8], lb[8];
#pragma unroll
    for (int j = 0; j < 8; j++) {
        float a = T[seg * 16 + 2 * j][f];
        float c = T[seg * 16 + 2 * j + 1][f];
        uint32_t h = pack_bf16(a, c);
        hb[j] = h;
        lb[j] = pack_bf16(a - bf_lo(h), c - bf_hi(h));
    }
    size_t o = (((size_t)b * 64 + f) * SS + s0 + seg * 16) >> 3;  // uint4 idx
    ((uint4*)g_VThi)[o] = make_uint4(hb[0], hb[1], hb[2], hb[3]);
    ((uint4*)g_VThi)[o + 1] = make_uint4(hb[4], hb[5], hb[6], hb[7]);
    ((uint4*)g_VTlo)[o] = make_uint4(lb[0], lb[1], lb[2], lb[3]);
    ((uint4*)g_VTlo)[o + 1] = make_uint4(lb[4], lb[5], lb[6], lb[7]);
}

// ---------------- Kernel 4: tensor-core fused attention ----------------
// Block: 64 q-rows, 4 warps x 16 q-rows. Key tiles of 64 (hi+lo in smem).
// smem per buffer: K tile [128 rows (hi 0-63, lo 64-127)][32 bf16, 80B stride]
//                  V tile [128 rows (hi f 0-63, lo 64-127)][64 bf16, 144B]
#define KBYTES (128 * 80)
#define VBYTES (128 * 144)
#define BUFBYTES (KBYTES + VBYTES)
#define SMEMB (2 * BUFBYTES)

__global__ __launch_bounds__(128, 5) void attn_kernel() {
    extern __shared__ __align__(16) char smem[];
    const uint32_t sbase = (uint32_t)__cvta_generic_to_shared(smem);

    const int tid = threadIdx.x;
    const int w = tid >> 5, lane = tid & 31;
    const int gid = lane >> 2, tg = lane & 3;
    const int bb = blockIdx.y;
    const int q0 = blockIdx.x * 64;
    const int half = blockIdx.z;
    const int kt0 = half * TILES;

    const int lmRow = ((lane >> 4) << 3) + (lane & 7);
    const int lmCh = ((lane >> 3) & 1) << 4;

    // ---- Q A-fragments in registers (hi/lo, 1 m-frag, 2 ksteps) ----
    uint32_t qh[2][4], ql[2][4];
    {
        const uint32_t* Qh =
            (const uint32_t*)g_Mhi + ((size_t)bb * SS + q0 + w * 16) * 16;
        const uint32_t* Ql =
            (const uint32_t*)g_Mlo + ((size_t)bb * SS + q0 + w * 16) * 16;
#pragma unroll
        for (int s = 0; s < 2; s++) {
            qh[s][0] = Qh[gid * 16 + s * 8 + tg];
            qh[s][1] = Qh[(gid + 8) * 16 + s * 8 + tg];
            qh[s][2] = Qh[gid * 16 + s * 8 + 4 + tg];
            qh[s][3] = Qh[(gid + 8) * 16 + s * 8 + 4 + tg];
            ql[s][0] = Ql[gid * 16 + s * 8 + tg];
            ql[s][1] = Ql[(gid + 8) * 16 + s * 8 + tg];
            ql[s][2] = Ql[gid * 16 + s * 8 + 4 + tg];
            ql[s][3] = Ql[(gid + 8) * 16 + s * 8 + 4 + tg];
        }
    }

    float of[8][4];
#pragma unroll
    for (int j = 0; j < 8; j++)
#pragma unroll
        for (int i = 0; i < 4; i++) of[j][i] = 0.f;
    float lsl = 0.f, lsh = 0.f;

    const int trow = tid & 63;
    const char* ksrc0 =
        (const char*)((tid >= 64) ? g_Mlo : g_Mhi) +
        ((size_t)bb * SS + (size_t)kt0 * 64 + trow) * 64;
    const char* vsrc0 = (const char*)((tid >= 64) ? g_VTlo : g_VThi) +
                        (((size_t)bb * 64 + trow) * SS + (size_t)kt0 * 64) * 2;

#define ISSUE_TILE(it, buf)                                          \
    do {                                                             \
        const char* ks = ksrc0 + (size_t)(it) * 64 * 64;             \
        const char* vs = vsrc0 + (size_t)(it) * 128;                 \
        uint32_t kd = sbase + (buf) * BUFBYTES + tid * 80;           \
        uint32_t vd = sbase + (buf) * BUFBYTES + KBYTES + tid * 144; \
        CP_ASYNC16(kd + 0, ks + 0);                                  \
        CP_ASYNC16(kd + 16, ks + 16);                                \
        CP_ASYNC16(kd + 32, ks + 32);                                \
        CP_ASYNC16(kd + 48, ks + 48);                                \
        _Pragma("unroll") for (int c = 0; c < 8; c++)                \
            CP_ASYNC16(vd + c * 16, vs + c * 16);                    \
        CP_COMMIT();                                                 \
    } while (0)

    ISSUE_TILE(0, 0);

#pragma unroll 1
    for (int it = 0; it < TILES; it++) {
        const int buf = it & 1;
        if (it + 1 < TILES) {
            ISSUE_TILE(it + 1, buf ^ 1);
            asm volatile("cp.async.wait_group 1;" ::: "memory");
        } else {
            asm volatile("cp.async.wait_group 0;" ::: "memory");
        }
        __syncthreads();

        const uint32_t Kb = sbase + buf * BUFBYTES;
        const uint32_t Vb = Kb + KBYTES;

        // ---- fused per-32-key group: scores -> exp -> PV ----
#pragma unroll
        for (int g = 0; g < 2; g++) {
            float sf[2][2][4];  // [kk][jj][4]
#pragma unroll
            for (int kk = 0; kk < 2; kk++) {
                const int ka = g * 2 + kk;
                uint32_t bh0[4], bh1[4], bl0[4], bl1[4];
                ldmx4(bh0, Kb + (ka * 16 + lmRow) * 80 + lmCh);
                ldmx4(bh1, Kb + (ka * 16 + lmRow) * 80 + 32 + lmCh);
                ldmx4(bl0, Kb + (64 + ka * 16 + lmRow) * 80 + lmCh);
                ldmx4(bl1, Kb + (64 + ka * 16 + lmRow) * 80 + 32 + lmCh);
#pragma unroll
                for (int jj = 0; jj < 2; jj++) {
                    float* sa = sf[kk][jj];
#pragma unroll
                    for (int i = 0; i < 4; i++) sa[i] = 0.f;
                    mma_bf16(sa, qh[0], bh0 + jj * 2);
                    mma_bf16(sa, ql[0], bh0 + jj * 2);
                    mma_bf16(sa, qh[1], bh1 + jj * 2);
                    mma_bf16(sa, ql[1], bh1 + jj * 2);
                    mma_bf16(sa, qh[0], bl0 + jj * 2);
                    mma_bf16(sa, qh[1], bl1 + jj * 2);
                }
            }

            // exp + pack P (bf16); row sums from ROUNDED p for cancellation
            uint32_t phi[2][4];  // [kk]
#pragma unroll
            for (int kk = 0; kk < 2; kk++)
#pragma unroll
                for (int jj = 0; jj < 2; jj++) {
                    float p0 = fast_exp40(sf[kk][jj][0]);
                    float p1 = fast_exp40(sf[kk][jj][1]);
                    float p2 = fast_exp40(sf[kk][jj][2]);
                    float p3 = fast_exp40(sf[kk][jj][3]);
                    uint32_t h01 = pack_bf16(p0, p1);
                    uint32_t h23 = pack_bf16(p2, p3);
                    phi[kk][jj * 2] = h01;
                    phi[kk][jj * 2 + 1] = h23;
                    lsl += bf_lo(h01) + bf_hi(h01);
                    lsh += bf_lo(h23) + bf_hi(h23);
                }

            // PV for this 32-key group: O += P * (Vhi + Vlo)
#pragma unroll
            for (int jp = 0; jp < 4; jp++) {
#pragma unroll
                for (int kk = 0; kk < 2; kk++) {
                    const int ka = g * 2 + kk;
                    uint32_t vh[4], vl[4];
                    ldmx4(vh, Vb + (jp * 16 + lmRow) * 144 + ka * 32 + lmCh);
                    ldmx4(vl,
                          Vb + (64 + jp * 16 + lmRow) * 144 + ka * 32 + lmCh);
#pragma unroll
                    for (int jj = 0; jj < 2; jj++) {
                        float* oa = of[jp * 2 + jj];
                        mma_bf16(oa, phi[kk], vh + jj * 2);
                        mma_bf16(oa, phi[kk], vl + jj * 2);
                    }
                }
            }
        }
        __syncthreads();
    }

    // ---- row-sum reduce over the 4 tg-lanes ----
    lsl += __shfl_xor_sync(0xffffffffu, lsl, 1);
    lsl += __shfl_xor_sync(0xffffffffu, lsl, 2);
    lsh += __shfl_xor_sync(0xffffffffu, lsh, 1);
    lsh += __shfl_xor_sync(0xffffffffu, lsh, 2);

    // ---- write partials ----
    float* pobase =
        g_po + ((size_t)half * SB * SS + (size_t)bb * SS + q0 + w * 16) * SF;
    float* plbase =
        g_pl + (size_t)half * SB * SS + (size_t)bb * SS + q0 + w * 16;
    const int rlo = gid, rhi = gid + 8;
#pragma unroll
    for (int j = 0; j < 8; j++) {
        *(float2*)(pobase + (size_t)rlo * SF + j * 8 + tg * 2) =
            make_float2(of[j][0], of[j][1]);
        *(float2*)(pobase + (size_t)rhi * SF + j * 8 + tg * 2) =
            make_float2(of[j][2], of[j][3]);
    }
    if (tg == 0) {
        plbase[rlo] = lsl;
        plbase[rhi] = lsh;
    }
}

// ---------------- Kernel 5: combine splits + Xw + bias ----------------
__global__ __launch_bounds__(256) void combine_kernel(
    const float* __restrict__ bias, float* __restrict__ Out) {
    const int idx = blockIdx.x * 256 + threadIdx.x;  // float4 index
    const int row = idx >> 4;
    float l = 0.f;
#pragma unroll
    for (int h = 0; h < NSPLIT; h++) l += g_pl[h * (SB * SS) + row];
    const float linv = 1.f / l;
    float4 acc = make_float4(0.f, 0.f, 0.f, 0.f);
#pragma unroll
    for (int h = 0; h < NSPLIT; h++) {
        const float4 o =
            ((const float4*)g_po)[(size_t)h * (SB * SS * SF / 4) + idx];
        acc.x += o.x;
        acc.y += o.y;
        acc.z += o.z;
        acc.w += o.w;
    }
    const float4 x4 = ((const float4*)g_Xw)[idx];
    const float4 b4 = ((const float4*)bias)[idx & 15];
    float4 r;
    r.x = x4.x + acc.x * linv + b4.x;
    r.y = x4.y + acc.y * linv + b4.y;
    r.z = x4.z + acc.z * linv + b4.z;
    r.w = x4.w + acc.w * linv + b4.w;
    ((float4*)Out)[idx] = r;
}

extern "C" void kernel_launch(void* const* d_in, const int* in_sizes, int n_in,
                              void* d_out, int out_size) {
    (void)in_sizes;
    (void)n_in;
    (void)out_size;
    const float* X = (const float*)d_in[0];
    const float* Mm = (const float*)d_in[1];
    const float* W = (const float*)d_in[2];
    const float* bias = (const float*)d_in[3];
    float* out = (float*)d_out;

    cudaFuncSetAttribute(attn_kernel,
                         cudaFuncAttributeMaxDynamicSharedMemorySize, SMEMB);

    xw_kernel<<<SB * SS / 64, 256>>>(X, W);
    msplit_kernel<<<(SB * SS * SK / 4) / 256, 256>>>(Mm);
    vt_kernel<<<dim3(SS / 64, SB), 256>>>();
    attn_kernel<<<dim3(SS / 64, SB, NSPLIT), 128, SMEMB>>>();
    combine_kernel<<<(SB * SS * SF / 4) / 256, 256>>>(bias, out);
}

// round 10
// speedup vs baseline: 1.2137x; 1.2137x over previous
#include <cuda_runtime.h>
#include <cuda_bf16.h>
#include <cstdint>

// Z = XW + softmax(relu(M M^T)) @ XW + bias
// B=4, S=4096, F=64, K=32, fp32.
// Fixed-shift softmax: relu clamps scores to [0, ~88]; exp(s-40) always
// finite/normal, and (sum p*v)/(sum p) == softmax exactly.
//
// Tensor path via arch-neutral mma.sync (m16n8k16 bf16), ldmatrix, cp.async.
// Scores: 3-term bf16 split (qh*kh + ql*kh + qh*kl).
// PV: P rounded to bf16; row sums computed from the ROUNDED p so softmax
// renormalization cancels P's rounding error. V keeps hi+lo terms.
// R7 structure (32 q-rows/warp, 128-row block, 3 blocks/SM) with NSPLIT=16
// for fine-grained wave packing (grid 2048 -> 4.61 waves, ~8% tail).

#define SB 4
#define SS 4096
#define SF 64
#define SK 32
#define NSPLIT 16
#define TILES (SS / NSPLIT / 64)  // 4 key tiles of 64 per block

static __device__ float g_Xw[SB * SS * SF];              // X @ W
static __device__ float g_po[NSPLIT * SB * SS * SF];     // partial o
static __device__ float g_pl[NSPLIT * SB * SS];          // partial row sums
static __device__ unsigned short g_Mhi[SB * SS * SK];    // M split hi
static __device__ unsigned short g_Mlo[SB * SS * SK];    // M split lo
static __device__ unsigned short g_VThi[SB * SF * SS];   // (Xw)^T split hi
static __device__ unsigned short g_VTlo[SB * SF * SS];   // (Xw)^T split lo

// ---------------- helpers ----------------
__device__ __forceinline__ uint32_t pack_bf16(float lo, float hi) {
    uint32_t r;
    asm("cvt.rn.bf16x2.f32 %0, %1, %2;" : "=r"(r) : "f"(hi), "f"(lo));
    return r;
}
__device__ __forceinline__ float bf_lo(uint32_t p) {
    return __uint_as_float(p << 16);
}
__device__ __forceinline__ float bf_hi(uint32_t p) {
    return __uint_as_float(p & 0xffff0000u);
}
__device__ __forceinline__ float fast_exp40(float s) {
    // exp(max(s,0) - 40) = 2^(max(s,0)*log2e - 40*log2e)
    float t = fmaxf(s, 0.f) * 1.44269504089f - 57.7078016356f;
    float r;
    asm("ex2.approx.f32 %0, %1;" : "=f"(r) : "f"(t));
    return r;
}
__device__ __forceinline__ void mma_bf16(float* d, const uint32_t* a,
                                         const uint32_t* b) {
    asm volatile(
        "mma.sync.aligned.m16n8k16.row.col.f32.bf16.bf16.f32 "
        "{%0,%1,%2,%3}, {%4,%5,%6,%7}, {%8,%9}, {%0,%1,%2,%3};"
        : "+f"(d[0]), "+f"(d[1]), "+f"(d[2]), "+f"(d[3])
        : "r"(a[0]), "r"(a[1]), "r"(a[2]), "r"(a[3]), "r"(b[0]), "r"(b[1]));
}
__device__ __forceinline__ void ldmx4(uint32_t* r, uint32_t addr) {
    asm volatile(
        "ldmatrix.sync.aligned.m8n8.x4.shared.b16 {%0,%1,%2,%3}, [%4];"
        : "=r"(r[0]), "=r"(r[1]), "=r"(r[2]), "=r"(r[3])
        : "r"(addr));
}
#define CP_ASYNC16(dst, src)                                    \
    asm volatile("cp.async.cg.shared.global [%0], [%1], 16;" :: \
                     "r"(dst), "l"(src))
#define CP_COMMIT() asm volatile("cp.async.commit_group;" ::: "memory")

// ---------------- Kernel 1: Xw = X @ W ----------------
__global__ __launch_bounds__(256) void xw_kernel(const float* __restrict__ X,
                                                 const float* __restrict__ W) {
    __shared__ __align__(16) float Ws[64 * 64];
    __shared__ __align__(16) float Xs[64 * 64];
    const int tid = threadIdx.x;
    const int row0 = blockIdx.x * 64;

    const float4* Wg = (const float4*)W;
    float4* Ws4 = (float4*)Ws;
#pragma unroll
    for (int i = 0; i < 4; i++) Ws4[tid + i * 256] = Wg[tid + i * 256];
    const float4* Xg = (const float4*)(X + (size_t)row0 * 64);
    float4* Xs4 = (float4*)Xs;
#pragma unroll
    for (int i = 0; i < 4; i++) Xs4[tid + i * 256] = Xg[tid + i * 256];
    __syncthreads();

    const int a = tid >> 4, c = tid & 15;
    float acc[4][4] = {};
#pragma unroll 16
    for (int k = 0; k < 64; k++) {
        float4 w4 = *(const float4*)(Ws + k * 64 + c * 4);
#pragma unroll
        for (int r = 0; r < 4; r++) {
            float xv = Xs[(a * 4 + r) * 64 + k];
            acc[r][0] += xv * w4.x;
            acc[r][1] += xv * w4.y;
            acc[r][2] += xv * w4.z;
            acc[r][3] += xv * w4.w;
        }
    }
    float* out = g_Xw + (size_t)row0 * 64;
#pragma unroll
    for (int r = 0; r < 4; r++)
        *(float4*)(out + (a * 4 + r) * 64 + c * 4) =
            make_float4(acc[r][0], acc[r][1], acc[r][2], acc[r][3]);
}

// ---------------- Kernel 2: split M into bf16 hi/lo ----------------
__global__ __launch_bounds__(256) void msplit_kernel(
    const float* __restrict__ M) {
    const int i = blockIdx.x * 256 + threadIdx.x;  // float4 index
    float4 v = ((const float4*)M)[i];
    uint32_t h0 = pack_bf16(v.x, v.y), h1 = pack_bf16(v.z, v.w);
    uint32_t l0 = pack_bf16(v.x - bf_lo(h0), v.y - bf_hi(h0));
    uint32_t l1 = pack_bf16(v.z - bf_lo(h1), v.w - bf_hi(h1));
    ((uint2*)g_Mhi)[i] = make_uint2(h0, h1);
    ((uint2*)g_Mlo)[i] = make_uint2(l0, l1);
}

// ---------------- Kernel 3: V^T = (Xw)^T split into bf16 hi/lo -----
__global__ __launch_bounds__(256) void vt_kernel() {
    __shared__ float T[64][65];
    const int tid = threadIdx.x;
    const int b = blockIdx.y, s0 = blockIdx.x * 64;
    const float4* src = (const float4*)(g_Xw + ((size_t)b * SS + s0) * SF);
#pragma unroll
    for (int k = 0; k < 4; k++) {
        int idx = tid + k * 256;
        int r = idx >> 4, c = idx & 15;
        float4 v = src[idx];
        T[r][c * 4 + 0] = v.x;
        T[r][c * 4 + 1] = v.y;
        T[r][c * 4 + 2] = v.z;
        T[r][c * 4 + 3] = v.w;
    }
    __syncthreads();
    const int f = tid >> 2, seg = tid & 3;
    uint32_t hb[8], lb[8];
#pragma unroll
    for (int j = 0; j < 8; j++) {
        float a = T[seg * 16 + 2 * j][f];
        float c = T[seg * 16 + 2 * j + 1][f];
        uint32_t h = pack_bf16(a, c);
        hb[j] = h;
        lb[j] = pack_bf16(a - bf_lo(h), c - bf_hi(h));
    }
    size_t o = (((size_t)b * 64 + f) * SS + s0 + seg * 16) >> 3;  // uint4 idx
    ((uint4*)g_VThi)[o] = make_uint4(hb[0], hb[1], hb[2], hb[3]);
    ((uint4*)g_VThi)[o + 1] = make_uint4(hb[4], hb[5], hb[6], hb[7]);
    ((uint4*)g_VTlo)[o] = make_uint4(lb[0], lb[1], lb[2], lb[3]);
    ((uint4*)g_VTlo)[o + 1] = make_uint4(lb[4], lb[5], lb[6], lb[7]);
}

// ---------------- Kernel 4: tensor-core fused attention ----------------
// Block: 128 q-rows, 4 warps x 32 q-rows. Key tiles of 64 (hi+lo in smem).
// smem per buffer: K tile [128 rows (hi 0-63, lo 64-127)][32 bf16, 80B stride]
//                  V tile [128 rows (hi f 0-63, lo 64-127)][64 bf16, 144B]
#define KBYTES (128 * 80)
#define VBYTES (128 * 144)
#define BUFBYTES (KBYTES + VBYTES)
#define SMEMB (2 * BUFBYTES)

__global__ __launch_bounds__(128, 3) void attn_kernel() {
    extern __shared__ __align__(16) char smem[];
    const uint32_t sbase = (uint32_t)__cvta_generic_to_shared(smem);

    const int tid = threadIdx.x;
    const int w = tid >> 5, lane = tid & 31;
    const int gid = lane >> 2, tg = lane & 3;
    const int bb = blockIdx.y;
    const int q0 = blockIdx.x * 128;
    const int half = blockIdx.z;
    const int kt0 = half * TILES;

    const int lmRow = ((lane >> 4) << 3) + (lane & 7);
    const int lmCh = ((lane >> 3) & 1) << 4;

    // ---- Q A-fragments in registers (hi/lo, 2 m-frags, 2 ksteps) ----
    uint32_t qh[2][2][4], ql[2][2][4];
    {
        const uint32_t* Qh =
            (const uint32_t*)g_Mhi + ((size_t)bb * SS + q0 + w * 32) * 16;
        const uint32_t* Ql =
            (const uint32_t*)g_Mlo + ((size_t)bb * SS + q0 + w * 32) * 16;
#pragma unroll
        for (int m = 0; m < 2; m++)
#pragma unroll
            for (int s = 0; s < 2; s++) {
                int r0 = m * 16 + gid;
                qh[m][s][0] = Qh[r0 * 16 + s * 8 + tg];
                qh[m][s][1] = Qh[(r0 + 8) * 16 + s * 8 + tg];
                qh[m][s][2] = Qh[r0 * 16 + s * 8 + 4 + tg];
                qh[m][s][3] = Qh[(r0 + 8) * 16 + s * 8 + 4 + tg];
                ql[m][s][0] = Ql[r0 * 16 + s * 8 + tg];
                ql[m][s][1] = Ql[(r0 + 8) * 16 + s * 8 + tg];
                ql[m][s][2] = Ql[r0 * 16 + s * 8 + 4 + tg];
                ql[m][s][3] = Ql[(r0 + 8) * 16 + s * 8 + 4 + tg];
            }
    }

    float of[2][8][4];
#pragma unroll
    for (int m = 0; m < 2; m++)
#pragma unroll
        for (int j = 0; j < 8; j++)
#pragma unroll
            for (int i = 0; i < 4; i++) of[m][j][i] = 0.f;
    float lsl[2] = {0.f, 0.f}, lsh[2] = {0.f, 0.f};

    const int trow = tid & 63;
    const char* ksrc0 =
        (const char*)((tid >= 64) ? g_Mlo : g_Mhi) +
        ((size_t)bb * SS + (size_t)kt0 * 64 + trow) * 64;
    const char* vsrc0 = (const char*)((tid >= 64) ? g_VTlo : g_VThi) +
                        (((size_t)bb * 64 + trow) * SS + (size_t)kt0 * 64) * 2;

#define ISSUE_TILE(it, buf)                                          \
    do {                                                             \
        const char* ks = ksrc0 + (size_t)(it) * 64 * 64;             \
        const char* vs = vsrc0 + (size_t)(it) * 128;                 \
        uint32_t kd = sbase + (buf) * BUFBYTES + tid * 80;           \
        uint32_t vd = sbase + (buf) * BUFBYTES + KBYTES + tid * 144; \
        CP_ASYNC16(kd + 0, ks + 0);                                  \
        CP_ASYNC16(kd + 16, ks + 16);                                \
        CP_ASYNC16(kd + 32, ks + 32);                                \
        CP_ASYNC16(kd + 48, ks + 48);                                \
        _Pragma("unroll") for (int c = 0; c < 8; c++)                \
            CP_ASYNC16(vd + c * 16, vs + c * 16);                    \
        CP_COMMIT();                                                 \
    } while (0)

    ISSUE_TILE(0, 0);

#pragma unroll 1
    for (int it = 0; it < TILES; it++) {
        const int buf = it & 1;
        if (it + 1 < TILES) {
            ISSUE_TILE(it + 1, buf ^ 1);
            asm volatile("cp.async.wait_group 1;" ::: "memory");
        } else {
            asm volatile("cp.async.wait_group 0;" ::: "memory");
        }
        __syncthreads();

        const uint32_t Kb = sbase + buf * BUFBYTES;
        const uint32_t Vb = Kb + KBYTES;

        // ---- fused per-32-key group: scores -> exp -> PV ----
#pragma unroll
        for (int g = 0; g < 2; g++) {
            float sf[2][2][2][4];  // [kk][m][jj][4]
#pragma unroll
            for (int kk = 0; kk < 2; kk++) {
                const int ka = g * 2 + kk;
                uint32_t bh0[4], bh1[4], bl0[4], bl1[4];
                ldmx4(bh0, Kb + (ka * 16 + lmRow) * 80 + lmCh);
                ldmx4(bh1, Kb + (ka * 16 + lmRow) * 80 + 32 + lmCh);
                ldmx4(bl0, Kb + (64 + ka * 16 + lmRow) * 80 + lmCh);
                ldmx4(bl1, Kb + (64 + ka * 16 + lmRow) * 80 + 32 + lmCh);
#pragma unroll
                for (int m = 0; m < 2; m++)
#pragma unroll
                    for (int jj = 0; jj < 2; jj++) {
                        float* sa = sf[kk][m][jj];
#pragma unroll
                        for (int i = 0; i < 4; i++) sa[i] = 0.f;
                        mma_bf16(sa, qh[m][0], bh0 + jj * 2);
                        mma_bf16(sa, ql[m][0], bh0 + jj * 2);
                        mma_bf16(sa, qh[m][1], bh1 + jj * 2);
                        mma_bf16(sa, ql[m][1], bh1 + jj * 2);
                        mma_bf16(sa, qh[m][0], bl0 + jj * 2);
                        mma_bf16(sa, qh[m][1], bl1 + jj * 2);
                    }
            }

            // exp + pack P (bf16); row sums from ROUNDED p for cancellation
            uint32_t phi[2][2][4];  // [kk][m]
#pragma unroll
            for (int kk = 0; kk < 2; kk++)
#pragma unroll
                for (int m = 0; m < 2; m++)
#pragma unroll
                    for (int jj = 0; jj < 2; jj++) {
                        float p0 = fast_exp40(sf[kk][m][jj][0]);
                        float p1 = fast_exp40(sf[kk][m][jj][1]);
                        float p2 = fast_exp40(sf[kk][m][jj][2]);
                        float p3 = fast_exp40(sf[kk][m][jj][3]);
                        uint32_t h01 = pack_bf16(p0, p1);
                        uint32_t h23 = pack_bf16(p2, p3);
                        phi[kk][m][jj * 2] = h01;
                        phi[kk][m][jj * 2 + 1] = h23;
                        lsl[m] += bf_lo(h01) + bf_hi(h01);
                        lsh[m] += bf_lo(h23) + bf_hi(h23);
                    }

            // PV for this 32-key group: O += P * (Vhi + Vlo)
#pragma unroll
            for (int jp = 0; jp < 4; jp++) {
#pragma unroll
                for (int kk = 0; kk < 2; kk++) {
                    const int ka = g * 2 + kk;
                    uint32_t vh[4], vl[4];
                    ldmx4(vh, Vb + (jp * 16 + lmRow) * 144 + ka * 32 + lmCh);
                    ldmx4(vl,
                          Vb + (64 + jp * 16 + lmRow) * 144 + ka * 32 + lmCh);
#pragma unroll
                    for (int m = 0; m < 2; m++)
#pragma unroll
                        for (int jj = 0; jj < 2; jj++) {
                            float* oa = of[m][jp * 2 + jj];
                            mma_bf16(oa, phi[kk][m], vh + jj * 2);
                            mma_bf16(oa, phi[kk][m], vl + jj * 2);
                        }
                }
            }
        }
        __syncthreads();
    }

    // ---- row-sum reduce over the 4 tg-lanes ----
#pragma unroll
    for (int m = 0; m < 2; m++) {
        lsl[m] += __shfl_xor_sync(0xffffffffu, lsl[m], 1);
        lsl[m] += __shfl_xor_sync(0xffffffffu, lsl[m], 2);
        lsh[m] += __shfl_xor_sync(0xffffffffu, lsh[m], 1);
        lsh[m] += __shfl_xor_sync(0xffffffffu, lsh[m], 2);
    }

    // ---- write partials ----
    float* pobase =
        g_po + ((size_t)half * SB * SS + (size_t)bb * SS + q0 + w * 32) * SF;
    float* plbase =
        g_pl + (size_t)half * SB * SS + (size_t)bb * SS + q0 + w * 32;
#pragma unroll
    for (int m = 0; m < 2; m++) {
        int rlo = m * 16 + gid, rhi = rlo + 8;
#pragma unroll
        for (int j = 0; j < 8; j++) {
            *(float2*)(pobase + (size_t)rlo * SF + j * 8 + tg * 2) =
                make_float2(of[m][j][0], of[m][j][1]);
            *(float2*)(pobase + (size_t)rhi * SF + j * 8 + tg * 2) =
                make_float2(of[m][j][2], of[m][j][3]);
        }
        if (tg == 0) {
            plbase[rlo] = lsl[m];
            plbase[rhi] = lsh[m];
        }
    }
}

// ---------------- Kernel 5: combine splits + Xw + bias ----------------
__global__ __launch_bounds__(256) void combine_kernel(
    const float* __restrict__ bias, float* __restrict__ Out) {
    const int idx = blockIdx.x * 256 + threadIdx.x;  // float4 index
    const int row = idx >> 4;
    float l = 0.f;
#pragma unroll
    for (int h = 0; h < NSPLIT; h++) l += g_pl[h * (SB * SS) + row];
    const float linv = 1.f / l;
    float4 acc = make_float4(0.f, 0.f, 0.f, 0.f);
#pragma unroll
    for (int h = 0; h < NSPLIT; h++) {
        const float4 o =
            ((const float4*)g_po)[(size_t)h * (SB * SS * SF / 4) + idx];
        acc.x += o.x;
        acc.y += o.y;
        acc.z += o.z;
        acc.w += o.w;
    }
    const float4 x4 = ((const float4*)g_Xw)[idx];
    const float4 b4 = ((const float4*)bias)[idx & 15];
    float4 r;
    r.x = x4.x + acc.x * linv + b4.x;
    r.y = x4.y + acc.y * linv + b4.y;
    r.z = x4.z + acc.z * linv + b4.z;
    r.w = x4.w + acc.w * linv + b4.w;
    ((float4*)Out)[idx] = r;
}

extern "C" void kernel_launch(void* const* d_in, const int* in_sizes, int n_in,
                              void* d_out, int out_size) {
    (void)in_sizes;
    (void)n_in;
    (void)out_size;
    const float* X = (const float*)d_in[0];
    const float* Mm = (const float*)d_in[1];
    const float* W = (const float*)d_in[2];
    const float* bias = (const float*)d_in[3];
    float* out = (float*)d_out;

    cudaFuncSetAttribute(attn_kernel,
                         cudaFuncAttributeMaxDynamicSharedMemorySize, SMEMB);

    xw_kernel<<<SB * SS / 64, 256>>>(X, W);
    msplit_kernel<<<(SB * SS * SK / 4) / 256, 256>>>(Mm);
    vt_kernel<<<dim3(SS / 64, SB), 256>>>();
    attn_kernel<<<dim3(SS / 128, SB, NSPLIT), 128, SMEMB>>>();
    combine_kernel<<<(SB * SS * SF / 4) / 256, 256>>>(bias, out);
}

// round 11
// speedup vs baseline: 1.2998x; 1.0709x over previous
#include <cuda_runtime.h>
#include <cuda_bf16.h>
#include <cstdint>

// Z = XW + softmax(relu(M M^T)) @ XW + bias
// B=4, S=4096, F=64, K=32, fp32.
// Fixed-shift softmax: relu clamps scores to [0, ~88]; exp(s-40) always
// finite/normal, and (sum p*v)/(sum p) == softmax exactly.
//
// Tensor path via arch-neutral mma.sync (m16n8k16 bf16), ldmatrix, cp.async.
// Scores: 3-term bf16 split (qh*kh + ql*kh + qh*kl).
// PV: P rounded to bf16; row sums computed from the ROUNDED p so softmax
// renormalization cancels P's rounding error. V keeps hi+lo terms.
// attn = R7 validated config: 32 q-rows/warp, 128-row block, 3 blocks/SM,
// NSPLIT=8. Prep (XW + VT split + M split) fused into ONE kernel.

#define SB 4
#define SS 4096
#define SF 64
#define SK 32
#define NSPLIT 8
#define TILES (SS / NSPLIT / 64)  // 8 key tiles of 64 per block

static __device__ float g_Xw[SB * SS * SF];              // X @ W
static __device__ float g_po[NSPLIT * SB * SS * SF];     // partial o
static __device__ float g_pl[NSPLIT * SB * SS];          // partial row sums
static __device__ unsigned short g_Mhi[SB * SS * SK];    // M split hi
static __device__ unsigned short g_Mlo[SB * SS * SK];    // M split lo
static __device__ unsigned short g_VThi[SB * SF * SS];   // (Xw)^T split hi
static __device__ unsigned short g_VTlo[SB * SF * SS];   // (Xw)^T split lo

// ---------------- helpers ----------------
__device__ __forceinline__ uint32_t pack_bf16(float lo, float hi) {
    uint32_t r;
    asm("cvt.rn.bf16x2.f32 %0, %1, %2;" : "=r"(r) : "f"(hi), "f"(lo));
    return r;
}
__device__ __forceinline__ float bf_lo(uint32_t p) {
    return __uint_as_float(p << 16);
}
__device__ __forceinline__ float bf_hi(uint32_t p) {
    return __uint_as_float(p & 0xffff0000u);
}
__device__ __forceinline__ float fast_exp40(float s) {
    // exp(max(s,0) - 40) = 2^(max(s,0)*log2e - 40*log2e)
    float t = fmaxf(s, 0.f) * 1.44269504089f - 57.7078016356f;
    float r;
    asm("ex2.approx.f32 %0, %1;" : "=f"(r) : "f"(t));
    return r;
}
__device__ __forceinline__ void mma_bf16(float* d, const uint32_t* a,
                                         const uint32_t* b) {
    asm volatile(
        "mma.sync.aligned.m16n8k16.row.col.f32.bf16.bf16.f32 "
        "{%0,%1,%2,%3}, {%4,%5,%6,%7}, {%8,%9}, {%0,%1,%2,%3};"
        : "+f"(d[0]), "+f"(d[1]), "+f"(d[2]), "+f"(d[3])
        : "r"(a[0]), "r"(a[1]), "r"(a[2]), "r"(a[3]), "r"(b[0]), "r"(b[1]));
}
__device__ __forceinline__ void ldmx4(uint32_t* r, uint32_t addr) {
    asm volatile(
        "ldmatrix.sync.aligned.m8n8.x4.shared.b16 {%0,%1,%2,%3}, [%4];"
        : "=r"(r[0]), "=r"(r[1]), "=r"(r[2]), "=r"(r[3])
        : "r"(addr));
}
#define CP_ASYNC16(dst, src)                                    \
    asm volatile("cp.async.cg.shared.global [%0], [%1], 16;" :: \
                     "r"(dst), "l"(src))
#define CP_COMMIT() asm volatile("cp.async.commit_group;" ::: "memory")

// ---------------- Kernel 1: fused prep ----------------
// Blocks 0..255   : Xw tile (64 rows) = X @ W, write g_Xw AND the
//                   transposed bf16 hi/lo split g_VThi/g_VTlo.
// Blocks 256..767 : split M into g_Mhi/g_Mlo (elementwise).
__global__ __launch_bounds__(256) void prep_kernel(
    const float* __restrict__ X, const float* __restrict__ W,
    const float* __restrict__ M) {
    if (blockIdx.x >= 256) {
        // ---- msplit part ----
        const int i = (blockIdx.x - 256) * 256 + threadIdx.x;  // float4 idx
        float4 v = ((const float4*)M)[i];
        uint32_t h0 = pack_bf16(v.x, v.y), h1 = pack_bf16(v.z, v.w);
        uint32_t l0 = pack_bf16(v.x - bf_lo(h0), v.y - bf_hi(h0));
        uint32_t l1 = pack_bf16(v.z - bf_lo(h1), v.w - bf_hi(h1));
        ((uint2*)g_Mhi)[i] = make_uint2(h0, h1);
        ((uint2*)g_Mlo)[i] = make_uint2(l0, l1);
        return;
    }

    // ---- Xw part ----
    __shared__ __align__(16) float Ws[64 * 64];
    __shared__ __align__(16) float Xs[64 * 64];
    __shared__ float T[64 * 65];  // Xw tile, padded for transpose reads
    const int tid = threadIdx.x;
    const int row0 = blockIdx.x * 64;  // global row in [0, B*S)

    const float4* Wg = (const float4*)W;
    float4* Ws4 = (float4*)Ws;
#pragma unroll
    for (int i = 0; i < 4; i++) Ws4[tid + i * 256] = Wg[tid + i * 256];
    const float4* Xg = (const float4*)(X + (size_t)row0 * 64);
    float4* Xs4 = (float4*)Xs;
#pragma unroll
    for (int i = 0; i < 4; i++) Xs4[tid + i * 256] = Xg[tid + i * 256];
    __syncthreads();

    const int a = tid >> 4, c = tid & 15;
    float acc[4][4] = {};
#pragma unroll 16
    for (int k = 0; k < 64; k++) {
        float4 w4 = *(const float4*)(Ws + k * 64 + c * 4);
#pragma unroll
        for (int r = 0; r < 4; r++) {
            float xv = Xs[(a * 4 + r) * 64 + k];
            acc[r][0] += xv * w4.x;
            acc[r][1] += xv * w4.y;
            acc[r][2] += xv * w4.z;
            acc[r][3] += xv * w4.w;
        }
    }
    // write Xw (fp32) + stage tile for transpose
    float* out = g_Xw + (size_t)row0 * 64;
#pragma unroll
    for (int r = 0; r < 4; r++) {
        *(float4*)(out + (a * 4 + r) * 64 + c * 4) =
            make_float4(acc[r][0], acc[r][1], acc[r][2], acc[r][3]);
#pragma unroll
        for (int j = 0; j < 4; j++) T[(a * 4 + r) * 65 + c * 4 + j] = acc[r][j];
    }
    __syncthreads();

    // ---- transpose + bf16 hi/lo split -> g_VThi / g_VTlo ----
    const int b = row0 >> 12;        // row0 / SS
    const int s0 = row0 & (SS - 1);  // row0 % SS
    const int f = tid >> 2, seg = tid & 3;
    uint32_t hb[8], lb[8];
#pragma unroll
    for (int j = 0; j < 8; j++) {
        float aa = T[(seg * 16 + 2 * j) * 65 + f];
        float cc = T[(seg * 16 + 2 * j + 1) * 65 + f];
        uint32_t h = pack_bf16(aa, cc);
        hb[j] = h;
        lb[j] = pack_bf16(aa - bf_lo(h), cc - bf_hi(h));
    }
    size_t o = (((size_t)b * 64 + f) * SS + s0 + seg * 16) >> 3;  // uint4 idx
    ((uint4*)g_VThi)[o] = make_uint4(hb[0], hb[1], hb[2], hb[3]);
    ((uint4*)g_VThi)[o + 1] = make_uint4(hb[4], hb[5], hb[6], hb[7]);
    ((uint4*)g_VTlo)[o] = make_uint4(lb[0], lb[1], lb[2], lb[3]);
    ((uint4*)g_VTlo)[o + 1] = make_uint4(lb[4], lb[5], lb[6], lb[7]);
}

// ---------------- Kernel 2: tensor-core fused attention ----------------
// Block: 128 q-rows, 4 warps x 32 q-rows. Key tiles of 64 (hi+lo in smem).
// smem per buffer: K tile [128 rows (hi 0-63, lo 64-127)][32 bf16, 80B stride]
//                  V tile [128 rows (hi f 0-63, lo 64-127)][64 bf16, 144B]
#define KBYTES (128 * 80)
#define VBYTES (128 * 144)
#define BUFBYTES (KBYTES + VBYTES)
#define SMEMB (2 * BUFBYTES)

__global__ __launch_bounds__(128, 3) void attn_kernel() {
    extern __shared__ __align__(16) char smem[];
    const uint32_t sbase = (uint32_t)__cvta_generic_to_shared(smem);

    const int tid = threadIdx.x;
    const int w = tid >> 5, lane = tid & 31;
    const int gid = lane >> 2, tg = lane & 3;
    const int bb = blockIdx.y;
    const int q0 = blockIdx.x * 128;
    const int half = blockIdx.z;
    const int kt0 = half * TILES;

    const int lmRow = ((lane >> 4) << 3) + (lane & 7);
    const int lmCh = ((lane >> 3) & 1) << 4;

    // ---- Q A-fragments in registers (hi/lo, 2 m-frags, 2 ksteps) ----
    uint32_t qh[2][2][4], ql[2][2][4];
    {
        const uint32_t* Qh =
            (const uint32_t*)g_Mhi + ((size_t)bb * SS + q0 + w * 32) * 16;
        const uint32_t* Ql =
            (const uint32_t*)g_Mlo + ((size_t)bb * SS + q0 + w * 32) * 16;
#pragma unroll
        for (int m = 0; m < 2; m++)
#pragma unroll
            for (int s = 0; s < 2; s++) {
                int r0 = m * 16 + gid;
                qh[m][s][0] = Qh[r0 * 16 + s * 8 + tg];
                qh[m][s][1] = Qh[(r0 + 8) * 16 + s * 8 + tg];
                qh[m][s][2] = Qh[r0 * 16 + s * 8 + 4 + tg];
                qh[m][s][3] = Qh[(r0 + 8) * 16 + s * 8 + 4 + tg];
                ql[m][s][0] = Ql[r0 * 16 + s * 8 + tg];
                ql[m][s][1] = Ql[(r0 + 8) * 16 + s * 8 + tg];
                ql[m][s][2] = Ql[r0 * 16 + s * 8 + 4 + tg];
                ql[m][s][3] = Ql[(r0 + 8) * 16 + s * 8 + 4 + tg];
            }
    }

    float of[2][8][4];
#pragma unroll
    for (int m = 0; m < 2; m++)
#pragma unroll
        for (int j = 0; j < 8; j++)
#pragma unroll
            for (int i = 0; i < 4; i++) of[m][j][i] = 0.f;
    float lsl[2] = {0.f, 0.f}, lsh[2] = {0.f, 0.f};

    const int trow = tid & 63;
    const char* ksrc0 =
        (const char*)((tid >= 64) ? g_Mlo : g_Mhi) +
        ((size_t)bb * SS + (size_t)kt0 * 64 + trow) * 64;
    const char* vsrc0 = (const char*)((tid >= 64) ? g_VTlo : g_VThi) +
                        (((size_t)bb * 64 + trow) * SS + (size_t)kt0 * 64) * 2;

#define ISSUE_TILE(it, buf)                                          \
    do {                                                             \
        const char* ks = ksrc0 + (size_t)(it) * 64 * 64;             \
        const char* vs = vsrc0 + (size_t)(it) * 128;                 \
        uint32_t kd = sbase + (buf) * BUFBYTES + tid * 80;           \
        uint32_t vd = sbase + (buf) * BUFBYTES + KBYTES + tid * 144; \
        CP_ASYNC16(kd + 0, ks + 0);                                  \
        CP_ASYNC16(kd + 16, ks + 16);                                \
        CP_ASYNC16(kd + 32, ks + 32);                                \
        CP_ASYNC16(kd + 48, ks + 48);                                \
        _Pragma("unroll") for (int c = 0; c < 8; c++)                \
            CP_ASYNC16(vd + c * 16, vs + c * 16);                    \
        CP_COMMIT();                                                 \
    } while (0)

    ISSUE_TILE(0, 0);

#pragma unroll 1
    for (int it = 0; it < TILES; it++) {
        const int buf = it & 1;
        if (it + 1 < TILES) {
            ISSUE_TILE(it + 1, buf ^ 1);
            asm volatile("cp.async.wait_group 1;" ::: "memory");
        } else {
            asm volatile("cp.async.wait_group 0;" ::: "memory");
        }
        __syncthreads();

        const uint32_t Kb = sbase + buf * BUFBYTES;
        const uint32_t Vb = Kb + KBYTES;

        // ---- fused per-32-key group: scores -> exp -> PV ----
#pragma unroll
        for (int g = 0; g < 2; g++) {
            float sf[2][2][2][4];  // [kk][m][jj][4]
#pragma unroll
            for (int kk = 0; kk < 2; kk++) {
                const int ka = g * 2 + kk;
                uint32_t bh0[4], bh1[4], bl0[4], bl1[4];
                ldmx4(bh0, Kb + (ka * 16 + lmRow) * 80 + lmCh);
                ldmx4(bh1, Kb + (ka * 16 + lmRow) * 80 + 32 + lmCh);
                ldmx4(bl0, Kb + (64 + ka * 16 + lmRow) * 80 + lmCh);
                ldmx4(bl1, Kb + (64 + ka * 16 + lmRow) * 80 + 32 + lmCh);
#pragma unroll
                for (int m = 0; m < 2; m++)
#pragma unroll
                    for (int jj = 0; jj < 2; jj++) {
                        float* sa = sf[kk][m][jj];
#pragma unroll
                        for (int i = 0; i < 4; i++) sa[i] = 0.f;
                        mma_bf16(sa, qh[m][0], bh0 + jj * 2);
                        mma_bf16(sa, ql[m][0], bh0 + jj * 2);
                        mma_bf16(sa, qh[m][1], bh1 + jj * 2);
                        mma_bf16(sa, ql[m][1], bh1 + jj * 2);
                        mma_bf16(sa, qh[m][0], bl0 + jj * 2);
                        mma_bf16(sa, qh[m][1], bl1 + jj * 2);
                    }
            }

            // exp + pack P (bf16); row sums from ROUNDED p for cancellation
            uint32_t phi[2][2][4];  // [kk][m]
#pragma unroll
            for (int kk = 0; kk < 2; kk++)
#pragma unroll
                for (int m = 0; m < 2; m++)
#pragma unroll
                    for (int jj = 0; jj < 2; jj++) {
                        float p0 = fast_exp40(sf[kk][m][jj][0]);
                        float p1 = fast_exp40(sf[kk][m][jj][1]);
                        float p2 = fast_exp40(sf[kk][m][jj][2]);
                        float p3 = fast_exp40(sf[kk][m][jj][3]);
                        uint32_t h01 = pack_bf16(p0, p1);
                        uint32_t h23 = pack_bf16(p2, p3);
                        phi[kk][m][jj * 2] = h01;
                        phi[kk][m][jj * 2 + 1] = h23;
                        lsl[m] += bf_lo(h01) + bf_hi(h01);
                        lsh[m] += bf_lo(h23) + bf_hi(h23);
                    }

            // PV for this 32-key group: O += P * (Vhi + Vlo)
#pragma unroll
            for (int jp = 0; jp < 4; jp++) {
#pragma unroll
                for (int kk = 0; kk < 2; kk++) {
                    const int ka = g * 2 + kk;
                    uint32_t vh[4], vl[4];
                    ldmx4(vh, Vb + (jp * 16 + lmRow) * 144 + ka * 32 + lmCh);
                    ldmx4(vl,
                          Vb + (64 + jp * 16 + lmRow) * 144 + ka * 32 + lmCh);
#pragma unroll
                    for (int m = 0; m < 2; m++)
#pragma unroll
                        for (int jj = 0; jj < 2; jj++) {
                            float* oa = of[m][jp * 2 + jj];
                            mma_bf16(oa, phi[kk][m], vh + jj * 2);
                            mma_bf16(oa, phi[kk][m], vl + jj * 2);
                        }
                }
            }
        }
        __syncthreads();
    }

    // ---- row-sum reduce over the 4 tg-lanes ----
#pragma unroll
    for (int m = 0; m < 2; m++) {
        lsl[m] += __shfl_xor_sync(0xffffffffu, lsl[m], 1);
        lsl[m] += __shfl_xor_sync(0xffffffffu, lsl[m], 2);
        lsh[m] += __shfl_xor_sync(0xffffffffu, lsh[m], 1);
        lsh[m] += __shfl_xor_sync(0xffffffffu, lsh[m], 2);
    }

    // ---- write partials ----
    float* pobase =
        g_po + ((size_t)half * SB * SS + (size_t)bb * SS + q0 + w * 32) * SF;
    float* plbase =
        g_pl + (size_t)half * SB * SS + (size_t)bb * SS + q0 + w * 32;
#pragma unroll
    for (int m = 0; m < 2; m++) {
        int rlo = m * 16 + gid, rhi = rlo + 8;
#pragma unroll
        for (int j = 0; j < 8; j++) {
            *(float2*)(pobase + (size_t)rlo * SF + j * 8 + tg * 2) =
                make_float2(of[m][j][0], of[m][j][1]);
            *(float2*)(pobase + (size_t)rhi * SF + j * 8 + tg * 2) =
                make_float2(of[m][j][2], of[m][j][3]);
        }
        if (tg == 0) {
            plbase[rlo] = lsl[m];
            plbase[rhi] = lsh[m];
        }
    }
}

// ---------------- Kernel 3: combine splits + Xw + bias ----------------
__global__ __launch_bounds__(256) void combine_kernel(
    const float* __restrict__ bias, float* __restrict__ Out) {
    const int idx = blockIdx.x * 256 + threadIdx.x;  // float4 index
    const int row = idx >> 4;
    float l = 0.f;
#pragma unroll
    for (int h = 0; h < NSPLIT; h++) l += g_pl[h * (SB * SS) + row];
    const float linv = 1.f / l;
    float4 acc = make_float4(0.f, 0.f, 0.f, 0.f);
#pragma unroll
    for (int h = 0; h < NSPLIT; h++) {
        const float4 o =
            ((const float4*)g_po)[(size_t)h * (SB * SS * SF / 4) + idx];
        acc.x += o.x;
        acc.y += o.y;
        acc.z += o.z;
        acc.w += o.w;
    }
    const float4 x4 = ((const float4*)g_Xw)[idx];
    const float4 b4 = ((const float4*)bias)[idx & 15];
    float4 r;
    r.x = x4.x + acc.x * linv + b4.x;
    r.y = x4.y + acc.y * linv + b4.y;
    r.z = x4.z + acc.z * linv + b4.z;
    r.w = x4.w + acc.w * linv + b4.w;
    ((float4*)Out)[idx] = r;
}

extern "C" void kernel_launch(void* const* d_in, const int* in_sizes, int n_in,
                              void* d_out, int out_size) {
    (void)in_sizes;
    (void)n_in;
    (void)out_size;
    const float* X = (const float*)d_in[0];
    const float* Mm = (const float*)d_in[1];
    const float* W = (const float*)d_in[2];
    const float* bias = (const float*)d_in[3];
    float* out = (float*)d_out;

    cudaFuncSetAttribute(attn_kernel,
                         cudaFuncAttributeMaxDynamicSharedMemorySize, SMEMB);

    // 256 Xw+VT blocks + 512 M-split blocks in one launch
    prep_kernel<<<768, 256>>>(X, W, Mm);
    attn_kernel<<<dim3(SS / 128, SB, NSPLIT), 128, SMEMB>>>();
    combine_kernel<<<(SB * SS * SF / 4) / 256, 256>>>(bias, out);
}

// round 12
// speedup vs baseline: 1.3445x; 1.0344x over previous
#include <cuda_runtime.h>
#include <cuda_bf16.h>
#include <cstdint>

// Z = XW + softmax(relu(M M^T)) @ XW + bias
// B=4, S=4096, F=64, K=32, fp32.
// Fixed-shift softmax: relu clamps scores to [0, ~88]; exp(s-40) always
// finite/normal, and (sum p*v)/(sum p) == softmax exactly.
//
// Tensor path via arch-neutral mma.sync (m16n8k16 bf16), ldmatrix, cp.async.
// Scores: 3-term bf16 split (qh*kh + ql*kh + qh*kl).
// PV: P rounded to bf16; row sums computed from the ROUNDED p so softmax
// renormalization cancels P's rounding error. V keeps hi+lo terms.
// attn: R5 full-tile phase structure (16 parallel MMA chains per phase,
// 8 warps/SM) combined with R10's reduced math (no Plo term).

#define SB 4
#define SS 4096
#define SF 64
#define SK 32
#define NSPLIT 8
#define TILES (SS / NSPLIT / 64)  // 8 key tiles of 64 per block

static __device__ float g_Xw[SB * SS * SF];              // X @ W
static __device__ float g_po[NSPLIT * SB * SS * SF];     // partial o
static __device__ float g_pl[NSPLIT * SB * SS];          // partial row sums
static __device__ unsigned short g_Mhi[SB * SS * SK];    // M split hi
static __device__ unsigned short g_Mlo[SB * SS * SK];    // M split lo
static __device__ unsigned short g_VThi[SB * SF * SS];   // (Xw)^T split hi
static __device__ unsigned short g_VTlo[SB * SF * SS];   // (Xw)^T split lo

// ---------------- helpers ----------------
__device__ __forceinline__ uint32_t pack_bf16(float lo, float hi) {
    uint32_t r;
    asm("cvt.rn.bf16x2.f32 %0, %1, %2;" : "=r"(r) : "f"(hi), "f"(lo));
    return r;
}
__device__ __forceinline__ float bf_lo(uint32_t p) {
    return __uint_as_float(p << 16);
}
__device__ __forceinline__ float bf_hi(uint32_t p) {
    return __uint_as_float(p & 0xffff0000u);
}
__device__ __forceinline__ float fast_exp40(float s) {
    // exp(max(s,0) - 40) = 2^(max(s,0)*log2e - 40*log2e)
    float t = fmaxf(s, 0.f) * 1.44269504089f - 57.7078016356f;
    float r;
    asm("ex2.approx.f32 %0, %1;" : "=f"(r) : "f"(t));
    return r;
}
__device__ __forceinline__ void mma_bf16(float* d, const uint32_t* a,
                                         const uint32_t* b) {
    asm volatile(
        "mma.sync.aligned.m16n8k16.row.col.f32.bf16.bf16.f32 "
        "{%0,%1,%2,%3}, {%4,%5,%6,%7}, {%8,%9}, {%0,%1,%2,%3};"
        : "+f"(d[0]), "+f"(d[1]), "+f"(d[2]), "+f"(d[3])
        : "r"(a[0]), "r"(a[1]), "r"(a[2]), "r"(a[3]), "r"(b[0]), "r"(b[1]));
}
__device__ __forceinline__ void ldmx4(uint32_t* r, uint32_t addr) {
    asm volatile(
        "ldmatrix.sync.aligned.m8n8.x4.shared.b16 {%0,%1,%2,%3}, [%4];"
        : "=r"(r[0]), "=r"(r[1]), "=r"(r[2]), "=r"(r[3])
        : "r"(addr));
}
#define CP_ASYNC16(dst, src)                                    \
    asm volatile("cp.async.cg.shared.global [%0], [%1], 16;" :: \
                     "r"(dst), "l"(src))
#define CP_COMMIT() asm volatile("cp.async.commit_group;" ::: "memory")

// ---------------- Kernel 1: fused prep ----------------
// Blocks 0..255   : Xw tile (64 rows) = X @ W, write g_Xw AND the
//                   transposed bf16 hi/lo split g_VThi/g_VTlo.
// Blocks 256..767 : split M into g_Mhi/g_Mlo (elementwise).
__global__ __launch_bounds__(256) void prep_kernel(
    const float* __restrict__ X, const float* __restrict__ W,
    const float* __restrict__ M) {
    if (blockIdx.x >= 256) {
        // ---- msplit part ----
        const int i = (blockIdx.x - 256) * 256 + threadIdx.x;  // float4 idx
        float4 v = ((const float4*)M)[i];
        uint32_t h0 = pack_bf16(v.x, v.y), h1 = pack_bf16(v.z, v.w);
        uint32_t l0 = pack_bf16(v.x - bf_lo(h0), v.y - bf_hi(h0));
        uint32_t l1 = pack_bf16(v.z - bf_lo(h1), v.w - bf_hi(h1));
        ((uint2*)g_Mhi)[i] = make_uint2(h0, h1);
        ((uint2*)g_Mlo)[i] = make_uint2(l0, l1);
        return;
    }

    // ---- Xw part ----
    __shared__ __align__(16) float Ws[64 * 64];
    __shared__ __align__(16) float Xs[64 * 64];
    __shared__ float T[64 * 65];  // Xw tile, padded for transpose reads
    const int tid = threadIdx.x;
    const int row0 = blockIdx.x * 64;  // global row in [0, B*S)

    const float4* Wg = (const float4*)W;
    float4* Ws4 = (float4*)Ws;
#pragma unroll
    for (int i = 0; i < 4; i++) Ws4[tid + i * 256] = Wg[tid + i * 256];
    const float4* Xg = (const float4*)(X + (size_t)row0 * 64);
    float4* Xs4 = (float4*)Xs;
#pragma unroll
    for (int i = 0; i < 4; i++) Xs4[tid + i * 256] = Xg[tid + i * 256];
    __syncthreads();

    const int a = tid >> 4, c = tid & 15;
    float acc[4][4] = {};
#pragma unroll 16
    for (int k = 0; k < 64; k++) {
        float4 w4 = *(const float4*)(Ws + k * 64 + c * 4);
#pragma unroll
        for (int r = 0; r < 4; r++) {
            float xv = Xs[(a * 4 + r) * 64 + k];
            acc[r][0] += xv * w4.x;
            acc[r][1] += xv * w4.y;
            acc[r][2] += xv * w4.z;
            acc[r][3] += xv * w4.w;
        }
    }
    // write Xw (fp32) + stage tile for transpose
    float* out = g_Xw + (size_t)row0 * 64;
#pragma unroll
    for (int r = 0; r < 4; r++) {
        *(float4*)(out + (a * 4 + r) * 64 + c * 4) =
            make_float4(acc[r][0], acc[r][1], acc[r][2], acc[r][3]);
#pragma unroll
        for (int j = 0; j < 4; j++) T[(a * 4 + r) * 65 + c * 4 + j] = acc[r][j];
    }
    __syncthreads();

    // ---- transpose + bf16 hi/lo split -> g_VThi / g_VTlo ----
    const int b = row0 >> 12;        // row0 / SS
    const int s0 = row0 & (SS - 1);  // row0 % SS
    const int f = tid >> 2, seg = tid & 3;
    uint32_t hb[8], lb[8];
#pragma unroll
    for (int j = 0; j < 8; j++) {
        float aa = T[(seg * 16 + 2 * j) * 65 + f];
        float cc = T[(seg * 16 + 2 * j + 1) * 65 + f];
        uint32_t h = pack_bf16(aa, cc);
        hb[j] = h;
        lb[j] = pack_bf16(aa - bf_lo(h), cc - bf_hi(h));
    }
    size_t o = (((size_t)b * 64 + f) * SS + s0 + seg * 16) >> 3;  // uint4 idx
    ((uint4*)g_VThi)[o] = make_uint4(hb[0], hb[1], hb[2], hb[3]);
    ((uint4*)g_VThi)[o + 1] = make_uint4(hb[4], hb[5], hb[6], hb[7]);
    ((uint4*)g_VTlo)[o] = make_uint4(lb[0], lb[1], lb[2], lb[3]);
    ((uint4*)g_VTlo)[o + 1] = make_uint4(lb[4], lb[5], lb[6], lb[7]);
}

// ---------------- Kernel 2: tensor-core fused attention ----------------
// Block: 128 q-rows, 4 warps x 32 q-rows. Key tiles of 64 (hi+lo in smem).
// Full-tile phases: all scores (16 chains) -> all exp -> all PV (16 chains).
// smem per buffer: K tile [128 rows (hi 0-63, lo 64-127)][32 bf16, 80B stride]
//                  V tile [128 rows (hi f 0-63, lo 64-127)][64 bf16, 144B]
#define KBYTES (128 * 80)
#define VBYTES (128 * 144)
#define BUFBYTES (KBYTES + VBYTES)
#define SMEMB (2 * BUFBYTES)

__global__ __launch_bounds__(128, 2) void attn_kernel() {
    extern __shared__ __align__(16) char smem[];
    const uint32_t sbase = (uint32_t)__cvta_generic_to_shared(smem);

    const int tid = threadIdx.x;
    const int w = tid >> 5, lane = tid & 31;
    const int gid = lane >> 2, tg = lane & 3;
    const int bb = blockIdx.y;
    const int q0 = blockIdx.x * 128;
    const int half = blockIdx.z;
    const int kt0 = half * TILES;

    const int lmRow = ((lane >> 4) << 3) + (lane & 7);
    const int lmCh = ((lane >> 3) & 1) << 4;

    // ---- Q A-fragments in registers (hi/lo, 2 m-frags, 2 ksteps) ----
    uint32_t qh[2][2][4], ql[2][2][4];
    {
        const uint32_t* Qh =
            (const uint32_t*)g_Mhi + ((size_t)bb * SS + q0 + w * 32) * 16;
        const uint32_t* Ql =
            (const uint32_t*)g_Mlo + ((size_t)bb * SS + q0 + w * 32) * 16;
#pragma unroll
        for (int m = 0; m < 2; m++)
#pragma unroll
            for (int s = 0; s < 2; s++) {
                int r0 = m * 16 + gid;
                qh[m][s][0] = Qh[r0 * 16 + s * 8 + tg];
                qh[m][s][1] = Qh[(r0 + 8) * 16 + s * 8 + tg];
                qh[m][s][2] = Qh[r0 * 16 + s * 8 + 4 + tg];
                qh[m][s][3] = Qh[(r0 + 8) * 16 + s * 8 + 4 + tg];
                ql[m][s][0] = Ql[r0 * 16 + s * 8 + tg];
                ql[m][s][1] = Ql[(r0 + 8) * 16 + s * 8 + tg];
                ql[m][s][2] = Ql[r0 * 16 + s * 8 + 4 + tg];
                ql[m][s][3] = Ql[(r0 + 8) * 16 + s * 8 + 4 + tg];
            }
    }

    float of[2][8][4];
#pragma unroll
    for (int m = 0; m < 2; m++)
#pragma unroll
        for (int j = 0; j < 8; j++)
#pragma unroll
            for (int i = 0; i < 4; i++) of[m][j][i] = 0.f;
    float lsl[2] = {0.f, 0.f}, lsh[2] = {0.f, 0.f};

    const int trow = tid & 63;
    const char* ksrc0 =
        (const char*)((tid >= 64) ? g_Mlo : g_Mhi) +
        ((size_t)bb * SS + (size_t)kt0 * 64 + trow) * 64;
    const char* vsrc0 = (const char*)((tid >= 64) ? g_VTlo : g_VThi) +
                        (((size_t)bb * 64 + trow) * SS + (size_t)kt0 * 64) * 2;

#define ISSUE_TILE(it, buf)                                          \
    do {                                                             \
        const char* ks = ksrc0 + (size_t)(it) * 64 * 64;             \
        const char* vs = vsrc0 + (size_t)(it) * 128;                 \
        uint32_t kd = sbase + (buf) * BUFBYTES + tid * 80;           \
        uint32_t vd = sbase + (buf) * BUFBYTES + KBYTES + tid * 144; \
        CP_ASYNC16(kd + 0, ks + 0);                                  \
        CP_ASYNC16(kd + 16, ks + 16);                                \
        CP_ASYNC16(kd + 32, ks + 32);                                \
        CP_ASYNC16(kd + 48, ks + 48);                                \
        _Pragma("unroll") for (int c = 0; c < 8; c++)                \
            CP_ASYNC16(vd + c * 16, vs + c * 16);                    \
        CP_COMMIT();                                                 \
    } while (0)

    ISSUE_TILE(0, 0);

#pragma unroll 1
    for (int it = 0; it < TILES; it++) {
        const int buf = it & 1;
        if (it + 1 < TILES) {
            ISSUE_TILE(it + 1, buf ^ 1);
            asm volatile("cp.async.wait_group 1;" ::: "memory");
        } else {
            asm volatile("cp.async.wait_group 0;" ::: "memory");
        }
        __syncthreads();

        const uint32_t Kb = sbase + buf * BUFBYTES;
        const uint32_t Vb = Kb + KBYTES;

        // ---- phase 1: S = Q K^T (3-term split, 16 parallel chains) ----
        float sf[2][8][4];
#pragma unroll
        for (int m = 0; m < 2; m++)
#pragma unroll
            for (int j = 0; j < 8; j++)
#pragma unroll
                for (int i = 0; i < 4; i++) sf[m][j][i] = 0.f;

#pragma unroll
        for (int jp = 0; jp < 4; jp++) {
            uint32_t bh[2][4], bl[2][4];
#pragma unroll
            for (int s = 0; s < 2; s++) {
                ldmx4(bh[s], Kb + (jp * 16 + lmRow) * 80 + s * 32 + lmCh);
                ldmx4(bl[s],
                      Kb + (64 + jp * 16 + lmRow) * 80 + s * 32 + lmCh);
            }
#pragma unroll
            for (int m = 0; m < 2; m++)
#pragma unroll
                for (int jj = 0; jj < 2; jj++) {
                    float* sa = sf[m][jp * 2 + jj];
#pragma unroll
                    for (int s = 0; s < 2; s++) {
                        mma_bf16(sa, qh[m][s], bh[s] + jj * 2);
                        mma_bf16(sa, ql[m][s], bh[s] + jj * 2);
                        mma_bf16(sa, qh[m][s], bl[s] + jj * 2);
                    }
                }
        }

        // ---- phase 2: p = exp(relu(s)-40); pack bf16; row sums from
        //      ROUNDED p so softmax renormalization cancels the rounding ----
        uint32_t phi[2][4][4];
#pragma unroll
        for (int m = 0; m < 2; m++)
#pragma unroll
            for (int j = 0; j < 8; j++) {
                float p0 = fast_exp40(sf[m][j][0]);
                float p1 = fast_exp40(sf[m][j][1]);
                float p2 = fast_exp40(sf[m][j][2]);
                float p3 = fast_exp40(sf[m][j][3]);
                uint32_t h01 = pack_bf16(p0, p1);
                uint32_t h23 = pack_bf16(p2, p3);
                int ka = j >> 1, o = (j & 1) * 2;
                phi[m][ka][o] = h01;
                phi[m][ka][o + 1] = h23;
                lsl[m] += bf_lo(h01) + bf_hi(h01);
                lsh[m] += bf_lo(h23) + bf_hi(h23);
            }

        // ---- phase 3: O += P (Vhi + Vlo) (16 parallel chains) ----
#pragma unroll
        for (int jp = 0; jp < 4; jp++) {
#pragma unroll
            for (int ka = 0; ka < 4; ka++) {
                uint32_t vh[4], vl[4];
                ldmx4(vh, Vb + (jp * 16 + lmRow) * 144 + ka * 32 + lmCh);
                ldmx4(vl,
                      Vb + (64 + jp * 16 + lmRow) * 144 + ka * 32 + lmCh);
#pragma unroll
                for (int m = 0; m < 2; m++)
#pragma unroll
                    for (int jj = 0; jj < 2; jj++) {
                        float* oa = of[m][jp * 2 + jj];
                        mma_bf16(oa, phi[m][ka], vh + jj * 2);
                        mma_bf16(oa, phi[m][ka], vl + jj * 2);
                    }
            }
        }
        __syncthreads();
    }

    // ---- row-sum reduce over the 4 tg-lanes ----
#pragma unroll
    for (int m = 0; m < 2; m++) {
        lsl[m] += __shfl_xor_sync(0xffffffffu, lsl[m], 1);
        lsl[m] += __shfl_xor_sync(0xffffffffu, lsl[m], 2);
        lsh[m] += __shfl_xor_sync(0xffffffffu, lsh[m], 1);
        lsh[m] += __shfl_xor_sync(0xffffffffu, lsh[m], 2);
    }

    // ---- write partials ----
    float* pobase =
        g_po + ((size_t)half * SB * SS + (size_t)bb * SS + q0 + w * 32) * SF;
    float* plbase =
        g_pl + (size_t)half * SB * SS + (size_t)bb * SS + q0 + w * 32;
#pragma unroll
    for (int m = 0; m < 2; m++) {
        int rlo = m * 16 + gid, rhi = rlo + 8;
#pragma unroll
        for (int j = 0; j < 8; j++) {
            *(float2*)(pobase + (size_t)rlo * SF + j * 8 + tg * 2) =
                make_float2(of[m][j][0], of[m][j][1]);
            *(float2*)(pobase + (size_t)rhi * SF + j * 8 + tg * 2) =
                make_float2(of[m][j][2], of[m][j][3]);
        }
        if (tg == 0) {
            plbase[rlo] = lsl[m];
            plbase[rhi] = lsh[m];
        }
    }
}

// ---------------- Kernel 3: combine splits + Xw + bias ----------------
__global__ __launch_bounds__(256) void combine_kernel(
    const float* __restrict__ bias, float* __restrict__ Out) {
    const int idx = blockIdx.x * 256 + threadIdx.x;  // float4 index
    const int row = idx >> 4;
    float l = 0.f;
#pragma unroll
    for (int h = 0; h < NSPLIT; h++) l += g_pl[h * (SB * SS) + row];
    const float linv = 1.f / l;
    float4 acc = make_float4(0.f, 0.f, 0.f, 0.f);
#pragma unroll
    for (int h = 0; h < NSPLIT; h++) {
        const float4 o =
            ((const float4*)g_po)[(size_t)h * (SB * SS * SF / 4) + idx];
        acc.x += o.x;
        acc.y += o.y;
        acc.z += o.z;
        acc.w += o.w;
    }
    const float4 x4 = ((const float4*)g_Xw)[idx];
    const float4 b4 = ((const float4*)bias)[idx & 15];
    float4 r;
    r.x = x4.x + acc.x * linv + b4.x;
    r.y = x4.y + acc.y * linv + b4.y;
    r.z = x4.z + acc.z * linv + b4.z;
    r.w = x4.w + acc.w * linv + b4.w;
    ((float4*)Out)[idx] = r;
}

extern "C" void kernel_launch(void* const* d_in, const int* in_sizes, int n_in,
                              void* d_out, int out_size) {
    (void)in_sizes;
    (void)n_in;
    (void)out_size;
    const float* X = (const float*)d_in[0];
    const float* Mm = (const float*)d_in[1];
    const float* W = (const float*)d_in[2];
    const float* bias = (const float*)d_in[3];
    float* out = (float*)d_out;

    cudaFuncSetAttribute(attn_kernel,
                         cudaFuncAttributeMaxDynamicSharedMemorySize, SMEMB);

    // 256 Xw+VT blocks + 512 M-split blocks in one launch
    prep_kernel<<<768, 256>>>(X, W, Mm);
    attn_kernel<<<dim3(SS / 128, SB, NSPLIT), 128, SMEMB>>>();
    combine_kernel<<<(SB * SS * SF / 4) / 256, 256>>>(bias, out);
}